// round 2
// baseline (speedup 1.0000x reference)
#include <cuda_runtime.h>
#include <cuda_fp16.h>
#include <cstdint>

#define B_  256
#define T_  1024
#define H_  256
#define G4H 1024

#define MT 32      // batch tile (rows per group)
#define NT 64      // gate columns per CTA (16 hidden units x 4 gates, interleaved)
#define NGROUP 8   // B_/MT
#define NTILE  16  // G4H/NT

// -------- persistent device scratch (no allocations allowed) --------
__device__ __half   g_hbuf0[2 * B_ * H_];
__device__ __half   g_hbuf1[2 * B_ * H_];
__device__ __half   g_y0[(size_t)T_ * B_ * H_];   // layer-0 outputs, [T][B][H]
__device__ unsigned g_ctr0[NGROUP];
__device__ unsigned g_ctr1[NGROUP];

__global__ void init_kernel() {
    size_t idx = (size_t)blockIdx.x * blockDim.x + threadIdx.x;
    if (idx < (size_t)2 * B_ * H_) {
        g_hbuf0[idx] = __float2half(0.f);
        g_hbuf1[idx] = __float2half(0.f);
    }
    if (idx < NGROUP) { g_ctr0[idx] = 0u; g_ctr1[idx] = 0u; }
}

// -------- sync / math helpers --------
__device__ __forceinline__ unsigned ld_acq(const unsigned* p) {
    unsigned v;
    asm volatile("ld.acquire.gpu.global.u32 %0, [%1];" : "=r"(v) : "l"(p) : "memory");
    return v;
}
__device__ __forceinline__ void red_add_rel(unsigned* p) {
    asm volatile("red.release.gpu.global.add.u32 [%0], 1;" :: "l"(p) : "memory");
}
__device__ __forceinline__ float sigf(float x) {
    return __fdividef(1.f, 1.f + __expf(-x));
}
__device__ __forceinline__ float tanhf_fast(float x) {
    return 1.f - __fdividef(2.f, 1.f + __expf(2.f * x));
}
__device__ __forceinline__ void mma16816(float* d, const uint32_t* a, uint32_t b0, uint32_t b1) {
    asm volatile(
        "mma.sync.aligned.m16n8k16.row.col.f32.f16.f16.f32 "
        "{%0,%1,%2,%3}, {%4,%5,%6,%7}, {%8,%9}, {%0,%1,%2,%3};\n"
        : "+f"(d[0]), "+f"(d[1]), "+f"(d[2]), "+f"(d[3])
        : "r"(a[0]), "r"(a[1]), "r"(a[2]), "r"(a[3]), "r"(b0), "r"(b1));
}

// ====================================================================
// Persistent LSTM layer.
//   KDIM = 256 (layer 0: gates = h @ Whh^T + x*wih + bias)
//   KDIM = 512 (layer 1: gates = [y0_t | h] @ [Wih;Whh]^T + bias, fused)
// Gate columns are permuted: perm col n -> original row (n&3)*H + (n>>2),
// so each CTA's 64 columns are 16 complete (i,f,g,o) hidden units.
// ====================================================================
template <int KDIM, bool IS_L0>
__global__ __launch_bounds__(128, 1)
void lstm_layer_kernel(const float* __restrict__ x,
                       const float* __restrict__ Wih,
                       const float* __restrict__ Whh,
                       const float* __restrict__ bih,
                       const float* __restrict__ bhh,
                       float* __restrict__ out,
                       int layer_idx) {
    constexpr int RS  = KDIM + 8;   // smem row stride (halfs), dodges bank conflicts
    constexpr int GS  = 68;         // gate-dump row stride (floats), 16B-aligned rows
    constexpr int NKC = KDIM / 16;  // k-chunks

    extern __shared__ char smem_raw[];
    __half* As = (__half*)smem_raw;                       // [MT][RS]  A = [y0|h]
    __half* Ws = As + MT * RS;                            // [NT][RS]  (layer 1 only)
    float*  Gs = (float*)(smem_raw + (IS_L0 ? MT * RS * 2 : (MT + NT) * RS * 2));
    float*  bias_s = Gs + MT * GS;                        // [NT]
    float*  wx_s   = bias_s + NT;                         // [NT] (layer 0 only)
    float*  xs     = wx_s + NT;                           // [MT] (layer 0 only)

    const int tid  = threadIdx.x;
    const int lane = tid & 31, warp = tid >> 5;
    const int gid  = lane >> 2, tig = lane & 3;
    const int ntile = blockIdx.x, grp = blockIdx.y;
    const int n0 = ntile * NT;        // first (permuted) gate column
    const int b0 = grp * MT;          // first batch row
    const int j0 = n0 >> 2;           // first hidden unit owned by this CTA

    __half*   hbuf = IS_L0 ? g_hbuf0 : g_hbuf1;
    unsigned* ctr  = (IS_L0 ? g_ctr0 : g_ctr1) + grp;

    // --- one-time: bias (and scalar-input weight for layer 0) ---
    if (tid < NT) {
        int n_g = n0 + tid;
        int p   = (n_g & 3) * H_ + (n_g >> 2);
        bias_s[tid] = bih[p] + bhh[p];
        if (IS_L0) wx_s[tid] = Wih[p];   // W_ih0 is [4H,1]
    }

    // --- one-time: weights ---
    uint32_t bw[2][16][2];  // layer-0: B fragments resident in registers
    if constexpr (IS_L0) {
        #pragma unroll
        for (int ni = 0; ni < 2; ni++) {
            int n_g = n0 + warp * 16 + ni * 8 + gid;
            int p   = (n_g & 3) * H_ + (n_g >> 2);
            const float* wr = Whh + (size_t)p * H_;
            #pragma unroll
            for (int kc = 0; kc < 16; kc++) {
                int k = kc * 16 + tig * 2;
                __half2 h01 = __floats2half2_rn(wr[k], wr[k + 1]);
                __half2 h89 = __floats2half2_rn(wr[k + 8], wr[k + 9]);
                bw[ni][kc][0] = *(uint32_t*)&h01;
                bw[ni][kc][1] = *(uint32_t*)&h89;
            }
        }
    } else {
        // layer-1: [Wih1 | Whh1] concat along K, fp16 in smem
        for (int idx = tid; idx < NT * KDIM; idx += 128) {
            int nl = idx / KDIM, k = idx % KDIM;
            int n_g = n0 + nl;
            int p   = (n_g & 3) * H_ + (n_g >> 2);
            float v = (k < H_) ? Wih[(size_t)p * H_ + k]
                               : Whh[(size_t)p * H_ + (k - H_)];
            Ws[nl * RS + k] = __float2half_rn(v);
        }
    }
    __syncthreads();

    const int m   = tid >> 2;         // epilogue: batch row
    const int jjb = (tid & 3) * 4;    // epilogue: first of 4 hidden units
    float creg[4] = {0.f, 0.f, 0.f, 0.f};

    for (int t = 0; t < T_; ++t) {
        // ---- load A tile (h_prev, and y0[t] for layer 1) into smem ----
        const __half* hsrc = hbuf + (size_t)(t & 1) * (B_ * H_);
        {
            int row = tid >> 2, seg = tid & 3;
            if constexpr (IS_L0) {
                const uint4* src = (const uint4*)(hsrc + (size_t)(b0 + row) * H_ + seg * 64);
                uint4* dst = (uint4*)(As + row * RS + seg * 64);
                #pragma unroll
                for (int i = 0; i < 8; i++) dst[i] = src[i];
                if (tid < MT) xs[tid] = x[(size_t)(b0 + tid) * T_ + t];
            } else {
                const __half* src = (seg < 2)
                    ? (g_y0 + ((size_t)t * B_ + b0 + row) * H_ + seg * 128)
                    : (hsrc + (size_t)(b0 + row) * H_ + (seg - 2) * 128);
                const uint4* s4 = (const uint4*)src;
                uint4* dst = (uint4*)(As + row * RS + seg * 128);
                #pragma unroll
                for (int i = 0; i < 16; i++) dst[i] = s4[i];
            }
        }
        __syncthreads();

        // ---- MMA: acc[32 x 64] per CTA, warp owns 16 N-columns ----
        float acc[2][2][4];
        #pragma unroll
        for (int mi = 0; mi < 2; mi++)
            #pragma unroll
            for (int ni = 0; ni < 2; ni++)
                #pragma unroll
                for (int r = 0; r < 4; r++) acc[mi][ni][r] = 0.f;

        #pragma unroll
        for (int kc = 0; kc < NKC; kc++) {
            uint32_t a[2][4];
            #pragma unroll
            for (int mi = 0; mi < 2; mi++) {
                const __half* ab = As + (mi * 16 + gid) * RS + kc * 16 + tig * 2;
                a[mi][0] = *(const uint32_t*)(ab);
                a[mi][1] = *(const uint32_t*)(ab + 8 * RS);
                a[mi][2] = *(const uint32_t*)(ab + 8);
                a[mi][3] = *(const uint32_t*)(ab + 8 * RS + 8);
            }
            uint32_t bf[2][2];
            if constexpr (IS_L0) {
                #pragma unroll
                for (int ni = 0; ni < 2; ni++) {
                    bf[ni][0] = bw[ni][kc][0];
                    bf[ni][1] = bw[ni][kc][1];
                }
            } else {
                #pragma unroll
                for (int ni = 0; ni < 2; ni++) {
                    const __half* wb = Ws + (warp * 16 + ni * 8 + gid) * RS + kc * 16 + tig * 2;
                    bf[ni][0] = *(const uint32_t*)wb;
                    bf[ni][1] = *(const uint32_t*)(wb + 8);
                }
            }
            #pragma unroll
            for (int mi = 0; mi < 2; mi++)
                #pragma unroll
                for (int ni = 0; ni < 2; ni++)
                    mma16816(acc[mi][ni], a[mi], bf[ni][0], bf[ni][1]);
        }

        // ---- dump accumulators to smem so each thread gets 4 contiguous gates ----
        #pragma unroll
        for (int mi = 0; mi < 2; mi++)
            #pragma unroll
            for (int ni = 0; ni < 2; ni++) {
                float* gp = Gs + (mi * 16 + gid) * GS + warp * 16 + ni * 8 + tig * 2;
                *(float2*)gp            = make_float2(acc[mi][ni][0], acc[mi][ni][1]);
                *(float2*)(gp + 8 * GS) = make_float2(acc[mi][ni][2], acc[mi][ni][3]);
            }
        __syncthreads();

        // ---- elementwise: i,f,g,o -> c,h for 4 hidden units of one batch row ----
        float hv[4];
        float xv = IS_L0 ? xs[m] : 0.f;
        #pragma unroll
        for (int e = 0; e < 4; e++) {
            int nl = (jjb + e) * 4;
            const float4 gv = *(const float4*)(Gs + m * GS + nl);
            float pi = gv.x + bias_s[nl + 0];
            float pf = gv.y + bias_s[nl + 1];
            float pg = gv.z + bias_s[nl + 2];
            float po = gv.w + bias_s[nl + 3];
            if constexpr (IS_L0) {
                pi += xv * wx_s[nl + 0];
                pf += xv * wx_s[nl + 1];
                pg += xv * wx_s[nl + 2];
                po += xv * wx_s[nl + 3];
            }
            float ig = sigf(pi), fg = sigf(pf), gg = tanhf_fast(pg), og = sigf(po);
            float c  = fg * creg[e] + ig * gg;
            creg[e]  = c;
            hv[e]    = og * tanhf_fast(c);
        }

        // ---- publish h_t (fp16), double-buffered; layer 0 also writes y0 ----
        __half2 p01 = __floats2half2_rn(hv[0], hv[1]);
        __half2 p23 = __floats2half2_rn(hv[2], hv[3]);
        uint2 pk = make_uint2(*(uint32_t*)&p01, *(uint32_t*)&p23);
        __half* hdst = hbuf + (size_t)((t + 1) & 1) * (B_ * H_) +
                       (size_t)(b0 + m) * H_ + j0 + jjb;
        *(uint2*)hdst = pk;
        if constexpr (IS_L0) {
            __half* ydst = g_y0 + ((size_t)t * B_ + b0 + m) * H_ + j0 + jjb;
            *(uint2*)ydst = pk;
        }
        if (t == T_ - 1) {
            size_t oidx = ((size_t)layer_idx * B_ + (b0 + m)) * H_ + j0 + jjb;
            *(float4*)(out + oidx) = make_float4(hv[0], hv[1], hv[2], hv[3]);
            *(float4*)(out + (size_t)2 * B_ * H_ + oidx) =
                make_float4(creg[0], creg[1], creg[2], creg[3]);
        }

        // ---- per-group barrier: monotonic counter, release/acquire ----
        __threadfence();
        __syncthreads();
        if (tid == 0) {
            red_add_rel(ctr);
            const unsigned target = (unsigned)NTILE * (unsigned)(t + 1);
            while (ld_acq(ctr) < target) { }
        }
        __syncthreads();
    }
}

extern "C" void kernel_launch(void* const* d_in, const int* in_sizes, int n_in,
                              void* d_out, int out_size) {
    (void)in_sizes; (void)n_in; (void)out_size;
    const float* x    = (const float*)d_in[0];
    const float* Wih0 = (const float*)d_in[1];
    const float* Whh0 = (const float*)d_in[2];
    const float* bih0 = (const float*)d_in[3];
    const float* bhh0 = (const float*)d_in[4];
    const float* Wih1 = (const float*)d_in[5];
    const float* Whh1 = (const float*)d_in[6];
    const float* bih1 = (const float*)d_in[7];
    const float* bhh1 = (const float*)d_in[8];
    float* out = (float*)d_out;

    // smem: A (+W for L1) halfs, gate dump floats, bias/wx/xs floats
    const int smem_l0 = MT * (256 + 8) * 2 + MT * 68 * 4 + (NT + NT + MT) * 4;           // ~26 KB
    const int smem_l1 = (MT + NT) * (512 + 8) * 2 + MT * 68 * 4 + (NT + NT + MT) * 4;    // ~109 KB

    cudaFuncSetAttribute((const void*)&lstm_layer_kernel<256, true>,
                         cudaFuncAttributeMaxDynamicSharedMemorySize, smem_l0);
    cudaFuncSetAttribute((const void*)&lstm_layer_kernel<512, false>,
                         cudaFuncAttributeMaxDynamicSharedMemorySize, smem_l1);

    init_kernel<<<512, 256>>>();

    dim3 grid(NTILE, NGROUP);
    lstm_layer_kernel<256, true><<<grid, 128, smem_l0>>>(
        x, Wih0, Whh0, bih0, bhh0, out, 0);
    lstm_layer_kernel<512, false><<<grid, 128, smem_l1>>>(
        nullptr, Wih1, Whh1, bih1, bhh1, out, 1);
}

// round 3
// speedup vs baseline: 1.5234x; 1.5234x over previous
#include <cuda_runtime.h>
#include <cuda_fp16.h>
#include <cstdint>

#define B_  256
#define T_  1024
#define H_  256
#define G4H 1024

#define MT 32       // batch rows per group
#define NT 128      // permuted gate cols per CTA (32 hidden units x 4 gates)
#define NGROUP 8    // B_/MT
#define NTILE  8    // G4H/NT
#define THREADS 256

// -------- persistent device scratch (no allocations allowed) --------
__device__ __half   g_hbuf0[2 * B_ * H_];
__device__ __half   g_hbuf1[2 * B_ * H_];
__device__ __half   g_y0[(size_t)T_ * B_ * H_];   // layer-0 outputs [T][B][H]
__device__ unsigned g_ctr0[NGROUP];
__device__ unsigned g_ctr1[NGROUP];

__global__ void init_kernel() {
    size_t idx = (size_t)blockIdx.x * blockDim.x + threadIdx.x;
    if (idx < (size_t)2 * B_ * H_) {
        g_hbuf0[idx] = __float2half(0.f);
        g_hbuf1[idx] = __float2half(0.f);
    }
    if (idx < NGROUP) { g_ctr0[idx] = 0u; g_ctr1[idx] = 0u; }
}

// -------- helpers --------
__device__ __forceinline__ unsigned ld_acq(const unsigned* p) {
    unsigned v;
    asm volatile("ld.acquire.gpu.global.u32 %0, [%1];" : "=r"(v) : "l"(p) : "memory");
    return v;
}
__device__ __forceinline__ void red_add_rel(unsigned* p) {
    asm volatile("red.release.gpu.global.add.u32 [%0], 1;" :: "l"(p) : "memory");
}
__device__ __forceinline__ float tanh_hw(float x) {
    float y;
    asm("tanh.approx.f32 %0, %1;" : "=f"(y) : "f"(x));
    return y;
}
__device__ __forceinline__ float sig_hw(float x) {
    return fmaf(0.5f, tanh_hw(0.5f * x), 0.5f);
}
__device__ __forceinline__ void mma16816(float* d, const uint32_t* a, uint32_t b0, uint32_t b1) {
    asm volatile(
        "mma.sync.aligned.m16n8k16.row.col.f32.f16.f16.f32 "
        "{%0,%1,%2,%3}, {%4,%5,%6,%7}, {%8,%9}, {%0,%1,%2,%3};\n"
        : "+f"(d[0]), "+f"(d[1]), "+f"(d[2]), "+f"(d[3])
        : "r"(a[0]), "r"(a[1]), "r"(a[2]), "r"(a[3]), "r"(b0), "r"(b1));
}
__device__ __forceinline__ void ldsm4(uint32_t* r, uint32_t addr) {
    asm volatile("ldmatrix.sync.aligned.m8n8.x4.shared.b16 {%0,%1,%2,%3}, [%4];"
        : "=r"(r[0]), "=r"(r[1]), "=r"(r[2]), "=r"(r[3]) : "r"(addr));
}
__device__ __forceinline__ uint32_t smem_u32(const void* p) {
    return (uint32_t)__cvta_generic_to_shared(p);
}

// ====================================================================
// One persistent LSTM layer. Gate columns permuted: perm col n ->
// original row (n&3)*H + (n>>2), so each CTA owns complete hidden units.
//   L0: KDIM=256  gates = h @ Whh^T (+ x*wih + bias), W in registers
//   L1: KDIM=512  gates = [y0_t | h] @ [Wih;Whh]^T (+bias), W in smem
// Layer 1 consumes y0 via layer-0's per-group monotonic counter.
// ====================================================================
template <int KDIM, bool IS_L0>
__device__ __forceinline__ void run_layer(const float* __restrict__ x,
                                          const float* __restrict__ Wih,
                                          const float* __restrict__ Whh,
                                          const float* __restrict__ bih,
                                          const float* __restrict__ bhh,
                                          float* __restrict__ out,
                                          int layer_idx) {
    constexpr int RS  = KDIM + 8;   // smem A/W row stride (halfs)
    constexpr int GS  = NT + 4;     // gate-dump row stride (floats)
    constexpr int NKC = KDIM / 16;
    constexpr int HOFF = IS_L0 ? 0 : H_;   // where h lives in A's K-range

    extern __shared__ char smem_raw[];
    __half* As = (__half*)smem_raw;                         // [MT][RS]
    __half* Ws = As + MT * RS;                              // [NT][RS] (L1)
    float*  Gs = (float*)(smem_raw + (IS_L0 ? MT * RS * 2 : (MT + NT) * RS * 2));
    float*  bias_s = Gs + MT * GS;                          // [NT]
    float*  wx_s   = bias_s + NT;                           // [NT] (L0)
    float*  xs     = wx_s + NT;                             // [2][MT] (L0)

    const int tid  = threadIdx.x;
    const int lane = tid & 31, warp = tid >> 5;
    const int gid  = lane >> 2, tig = lane & 3;
    const int ntile = blockIdx.x, grp = blockIdx.y;
    const int n0 = ntile * NT;
    const int b0 = grp * MT;
    const int j0 = n0 >> 2;

    __half*   hbuf = IS_L0 ? g_hbuf0 : g_hbuf1;
    unsigned* ctr  = (IS_L0 ? g_ctr0 : g_ctr1) + grp;
    unsigned* ctr_up = g_ctr0 + grp;   // producer counter (used by L1)

    // ---- one-time: bias (+ scalar input weight for L0) ----
    if (tid < NT) {
        int n_g = n0 + tid;
        int p   = (n_g & 3) * H_ + (n_g >> 2);
        bias_s[tid] = bih[p] + bhh[p];
        if (IS_L0) wx_s[tid] = Wih[p];
    }

    // ---- one-time: weights ----
    uint32_t bw[2][IS_L0 ? 16 : 1][2];
    if constexpr (IS_L0) {
        #pragma unroll
        for (int ni = 0; ni < 2; ni++) {
            int n_g = n0 + warp * 16 + ni * 8 + gid;
            int p   = (n_g & 3) * H_ + (n_g >> 2);
            const float* wr = Whh + (size_t)p * H_;
            #pragma unroll
            for (int kc = 0; kc < 16; kc++) {
                int k = kc * 16 + tig * 2;
                __half2 h01 = __floats2half2_rn(wr[k], wr[k + 1]);
                __half2 h89 = __floats2half2_rn(wr[k + 8], wr[k + 9]);
                bw[ni][kc][0] = *(uint32_t*)&h01;
                bw[ni][kc][1] = *(uint32_t*)&h89;
            }
        }
        if (tid < MT) xs[tid] = x[(size_t)(b0 + tid) * T_];   // x[:,0]
    } else {
        for (int idx = tid; idx < NT * KDIM; idx += THREADS) {
            int nl = idx / KDIM, k = idx % KDIM;
            int n_g = n0 + nl;
            int p   = (n_g & 3) * H_ + (n_g >> 2);
            float v = (k < H_) ? Wih[(size_t)p * H_ + k]
                               : Whh[(size_t)p * H_ + (k - H_)];
            Ws[nl * RS + k] = __float2half_rn(v);
        }
        // prologue: wait for y0[0], load into A's first H_ columns
        while (ld_acq(ctr_up) < (unsigned)NTILE) { }
        int row = tid >> 3, seg = tid & 7;
        const uint4* src = (const uint4*)(g_y0 + (size_t)(b0 + row) * H_ + seg * 32);
        uint4* dst = (uint4*)(As + row * RS + seg * 32);
        #pragma unroll
        for (int i = 0; i < 4; i++) dst[i] = src[i];
    }

    // ---- per-lane ldmatrix addresses ----
    const uint32_t As_b = smem_u32(As);
    uint32_t aAddr[2];
    #pragma unroll
    for (int mi = 0; mi < 2; mi++) {
        int rA = mi * 16 + (lane & 15);
        int cA = ((lane >> 4) & 1) * 8;
        aAddr[mi] = As_b + (uint32_t)(rA * RS + cA) * 2u;
    }
    uint32_t bAddr = 0;
    if constexpr (!IS_L0) {
        int rB = warp * 16 + (lane & 7) + ((lane & 16) ? 8 : 0);
        int cB = (lane & 8) ? 8 : 0;
        bAddr = smem_u32(Ws) + (uint32_t)(rB * RS + cB) * 2u;
    }

    const int m     = tid >> 3;          // epilogue batch row
    const int ubase = (tid & 7) * 4;     // epilogue first local unit
    float creg[4] = {0.f, 0.f, 0.f, 0.f};

    for (int t = 0; t < T_; ++t) {
        // ---- load h_prev into A's h-region ----
        {
            int row = tid >> 3, seg = tid & 7;
            const uint4* src = (const uint4*)(hbuf + (size_t)(t & 1) * (B_ * H_) +
                                              (size_t)(b0 + row) * H_ + seg * 32);
            uint4* dst = (uint4*)(As + row * RS + HOFF + seg * 32);
            #pragma unroll
            for (int i = 0; i < 4; i++) dst[i] = src[i];
        }
        __syncthreads();

        // ---- MMA: 32 x 128 gates, warp owns 16 N-cols ----
        float acc[2][2][4];
        #pragma unroll
        for (int mi = 0; mi < 2; mi++)
            #pragma unroll
            for (int ni = 0; ni < 2; ni++)
                #pragma unroll
                for (int r = 0; r < 4; r++) acc[mi][ni][r] = 0.f;

        #pragma unroll
        for (int kc = 0; kc < NKC; kc++) {
            uint32_t a0[4], a1[4];
            ldsm4(a0, aAddr[0] + kc * 32u);
            ldsm4(a1, aAddr[1] + kc * 32u);
            if constexpr (IS_L0) {
                mma16816(acc[0][0], a0, bw[0][kc][0], bw[0][kc][1]);
                mma16816(acc[0][1], a0, bw[1][kc][0], bw[1][kc][1]);
                mma16816(acc[1][0], a1, bw[0][kc][0], bw[0][kc][1]);
                mma16816(acc[1][1], a1, bw[1][kc][0], bw[1][kc][1]);
            } else {
                uint32_t bb[4];
                ldsm4(bb, bAddr + kc * 32u);
                mma16816(acc[0][0], a0, bb[0], bb[1]);
                mma16816(acc[0][1], a0, bb[2], bb[3]);
                mma16816(acc[1][0], a1, bb[0], bb[1]);
                mma16816(acc[1][1], a1, bb[2], bb[3]);
            }
        }

        // ---- dump to smem so each thread owns whole units ----
        #pragma unroll
        for (int mi = 0; mi < 2; mi++)
            #pragma unroll
            for (int ni = 0; ni < 2; ni++) {
                float* gp = Gs + (mi * 16 + gid) * GS + warp * 16 + ni * 8 + tig * 2;
                *(float2*)gp            = make_float2(acc[mi][ni][0], acc[mi][ni][1]);
                *(float2*)(gp + 8 * GS) = make_float2(acc[mi][ni][2], acc[mi][ni][3]);
            }
        __syncthreads();

        // ---- elementwise for 4 hidden units of one row ----
        float hv[4];
        float xv = IS_L0 ? xs[(t & 1) * MT + m] : 0.f;
        #pragma unroll
        for (int e = 0; e < 4; e++) {
            int nl = (ubase + e) * 4;
            const float4 gv = *(const float4*)(Gs + m * GS + nl);
            float pi = gv.x + bias_s[nl + 0];
            float pf = gv.y + bias_s[nl + 1];
            float pg = gv.z + bias_s[nl + 2];
            float po = gv.w + bias_s[nl + 3];
            if constexpr (IS_L0) {
                pi += xv * wx_s[nl + 0];
                pf += xv * wx_s[nl + 1];
                pg += xv * wx_s[nl + 2];
                po += xv * wx_s[nl + 3];
            }
            float ig = sig_hw(pi), fg = sig_hw(pf);
            float gg = tanh_hw(pg), og = sig_hw(po);
            float c  = fg * creg[e] + ig * gg;
            creg[e]  = c;
            hv[e]    = og * tanh_hw(c);
        }

        // ---- publish h_t (fp16); L0 also writes y0 ----
        __half2 p01 = __floats2half2_rn(hv[0], hv[1]);
        __half2 p23 = __floats2half2_rn(hv[2], hv[3]);
        uint2 pk = make_uint2(*(uint32_t*)&p01, *(uint32_t*)&p23);
        *(uint2*)(hbuf + (size_t)((t + 1) & 1) * (B_ * H_) +
                  (size_t)(b0 + m) * H_ + j0 + ubase) = pk;
        if constexpr (IS_L0) {
            *(uint2*)(g_y0 + ((size_t)t * B_ + b0 + m) * H_ + j0 + ubase) = pk;
        }
        if (t == T_ - 1) {
            size_t oidx = ((size_t)layer_idx * B_ + (b0 + m)) * H_ + j0 + ubase;
            *(float4*)(out + oidx) = make_float4(hv[0], hv[1], hv[2], hv[3]);
            *(float4*)(out + (size_t)2 * B_ * H_ + oidx) =
                make_float4(creg[0], creg[1], creg[2], creg[3]);
        }

        // ---- tail prefetch (off the h critical path) ----
        if (t + 1 < T_) {
            if constexpr (IS_L0) {
                if (tid < MT)
                    xs[((t + 1) & 1) * MT + tid] = x[(size_t)(b0 + tid) * T_ + (t + 1)];
            } else {
                // wait for producer step t+1, then prefetch y0[t+1]
                const unsigned need = (unsigned)NTILE * (unsigned)(t + 2);
                while (ld_acq(ctr_up) < need) { }
                int row = tid >> 3, seg = tid & 7;
                const uint4* src = (const uint4*)(g_y0 +
                    ((size_t)(t + 1) * B_ + b0 + row) * H_ + seg * 32);
                uint4* dst = (uint4*)(As + row * RS + seg * 32);
                #pragma unroll
                for (int i = 0; i < 4; i++) dst[i] = src[i];
            }
        }

        // ---- per-group barrier (monotonic counter, release/acquire) ----
        __syncthreads();
        if (tid == 0) {
            __threadfence();
            red_add_rel(ctr);
            const unsigned target = (unsigned)NTILE * (unsigned)(t + 1);
            while (ld_acq(ctr) < target) { }
        }
        __syncthreads();
    }
}

__global__ __launch_bounds__(THREADS, 1)
void lstm_fused_kernel(const float* __restrict__ x,
                       const float* __restrict__ Wih0, const float* __restrict__ Whh0,
                       const float* __restrict__ bih0, const float* __restrict__ bhh0,
                       const float* __restrict__ Wih1, const float* __restrict__ Whh1,
                       const float* __restrict__ bih1, const float* __restrict__ bhh1,
                       float* __restrict__ out) {
    if (blockIdx.z == 0)
        run_layer<256, true >(x, Wih0, Whh0, bih0, bhh0, out, 0);
    else
        run_layer<512, false>(nullptr, Wih1, Whh1, bih1, bhh1, out, 1);
}

extern "C" void kernel_launch(void* const* d_in, const int* in_sizes, int n_in,
                              void* d_out, int out_size) {
    (void)in_sizes; (void)n_in; (void)out_size;
    const float* x    = (const float*)d_in[0];
    const float* Wih0 = (const float*)d_in[1];
    const float* Whh0 = (const float*)d_in[2];
    const float* bih0 = (const float*)d_in[3];
    const float* bhh0 = (const float*)d_in[4];
    const float* Wih1 = (const float*)d_in[5];
    const float* Whh1 = (const float*)d_in[6];
    const float* bih1 = (const float*)d_in[7];
    const float* bhh1 = (const float*)d_in[8];
    float* out = (float*)d_out;

    // L1 smem footprint (the larger of the two layouts):
    // A [32][520] + W [128][520] halfs, G [32][132] floats, bias/wx/xs
    const int RS1 = 512 + 8, GS = NT + 4;
    const int smem_bytes = (MT + NT) * RS1 * 2 + MT * GS * 4 + (NT + NT + 2 * MT) * 4;

    cudaFuncSetAttribute((const void*)&lstm_fused_kernel,
                         cudaFuncAttributeMaxDynamicSharedMemorySize, smem_bytes);

    init_kernel<<<512, 256>>>();

    dim3 grid(NTILE, NGROUP, 2);
    lstm_fused_kernel<<<grid, THREADS, smem_bytes>>>(
        x, Wih0, Whh0, bih0, bhh0, Wih1, Whh1, bih1, bhh1, out);
}

// round 4
// speedup vs baseline: 1.6200x; 1.0634x over previous
#include <cuda_runtime.h>
#include <cuda_fp16.h>
#include <cstdint>

#define B_  256
#define T_  1024
#define H_  256
#define G4H 1024

#define MT 32       // batch rows per group
#define NT 128      // permuted gate cols per CTA (32 hidden units x 4 gates)
#define NGROUP 8    // B_/MT
#define NTILE  8    // G4H/NT
#define THREADS 256

// -------- persistent device scratch (no allocations allowed) --------
__device__ __half   g_hbuf0[2 * B_ * H_];
__device__ __half   g_hbuf1[2 * B_ * H_];
__device__ __half   g_y0[(size_t)T_ * B_ * H_];   // layer-0 outputs [T][B][H]
__device__ unsigned g_ctr0[NGROUP];
__device__ unsigned g_ctr1[NGROUP];

__global__ void init_kernel() {
    size_t idx = (size_t)blockIdx.x * blockDim.x + threadIdx.x;
    if (idx < (size_t)2 * B_ * H_) {
        g_hbuf0[idx] = __float2half(0.f);
        g_hbuf1[idx] = __float2half(0.f);
    }
    if (idx < NGROUP) { g_ctr0[idx] = 0u; g_ctr1[idx] = 0u; }
}

// -------- helpers --------
__device__ __forceinline__ unsigned ld_acq(const unsigned* p) {
    unsigned v;
    asm volatile("ld.acquire.gpu.global.u32 %0, [%1];" : "=r"(v) : "l"(p) : "memory");
    return v;
}
__device__ __forceinline__ void red_add_rel(unsigned* p) {
    asm volatile("red.release.gpu.global.add.u32 [%0], 1;" :: "l"(p) : "memory");
}
__device__ __forceinline__ float tanh_hw(float x) {
    float y;
    asm("tanh.approx.f32 %0, %1;" : "=f"(y) : "f"(x));
    return y;
}
__device__ __forceinline__ float sig_hw(float x) {
    return fmaf(0.5f, tanh_hw(0.5f * x), 0.5f);
}
__device__ __forceinline__ void mma16816(float* d, const uint32_t* a, uint32_t b0, uint32_t b1) {
    asm volatile(
        "mma.sync.aligned.m16n8k16.row.col.f32.f16.f16.f32 "
        "{%0,%1,%2,%3}, {%4,%5,%6,%7}, {%8,%9}, {%0,%1,%2,%3};\n"
        : "+f"(d[0]), "+f"(d[1]), "+f"(d[2]), "+f"(d[3])
        : "r"(a[0]), "r"(a[1]), "r"(a[2]), "r"(a[3]), "r"(b0), "r"(b1));
}
__device__ __forceinline__ void ldsm4(uint32_t* r, uint32_t addr) {
    asm volatile("ldmatrix.sync.aligned.m8n8.x4.shared.b16 {%0,%1,%2,%3}, [%4];"
        : "=r"(r[0]), "=r"(r[1]), "=r"(r[2]), "=r"(r[3]) : "r"(addr));
}
__device__ __forceinline__ uint32_t smem_u32(const void* p) {
    return (uint32_t)__cvta_generic_to_shared(p);
}

// ====================================================================
// One persistent LSTM layer. Gate columns permuted: perm col n ->
// original row (n&3)*H + (n>>2), so each CTA owns complete hidden units.
//   L0: KDIM=256  gates = h @ Whh^T (+ x*wih + bias), W in registers
//   L1: KDIM=512  gates = [y0_t | h] @ [Wih;Whh]^T (+bias), W in smem
// Layer 1 consumes y0 via layer-0's per-group monotonic counter.
// ====================================================================
template <int KDIM, bool IS_L0>
__device__ __forceinline__ void run_layer(const float* __restrict__ x,
                                          const float* __restrict__ Wih,
                                          const float* __restrict__ Whh,
                                          const float* __restrict__ bih,
                                          const float* __restrict__ bhh,
                                          float* __restrict__ out,
                                          int layer_idx) {
    constexpr int RS  = KDIM + 8;   // smem A/W row stride (halfs)
    constexpr int GS  = NT + 4;     // gate-dump row stride (floats)
    constexpr int NKC = KDIM / 16;
    constexpr int HOFF = IS_L0 ? 0 : H_;   // where h lives in A's K-range

    extern __shared__ char smem_raw[];
    __half* As = (__half*)smem_raw;                         // [MT][RS]
    __half* Ws = As + MT * RS;                              // [NT][RS] (L1)
    float*  Gs = (float*)(smem_raw + (IS_L0 ? MT * RS * 2 : (MT + NT) * RS * 2));
    float*  bias_s = Gs + MT * GS;                          // [NT]
    float*  wx_s   = bias_s + NT;                           // [NT] (L0)
    float*  xs     = wx_s + NT;                             // [2][MT] (L0)

    const int tid  = threadIdx.x;
    const int lane = tid & 31, warp = tid >> 5;
    const int gid  = lane >> 2, tig = lane & 3;
    const int ntile = blockIdx.x, grp = blockIdx.y;
    const int n0 = ntile * NT;
    const int b0 = grp * MT;
    const int j0 = n0 >> 2;

    __half*   hbuf = IS_L0 ? g_hbuf0 : g_hbuf1;
    unsigned* ctr  = (IS_L0 ? g_ctr0 : g_ctr1) + grp;
    unsigned* ctr_up = g_ctr0 + grp;   // producer counter (used by L1)

    // ---- one-time: bias (+ scalar input weight for L0) ----
    if (tid < NT) {
        int n_g = n0 + tid;
        int p   = (n_g & 3) * H_ + (n_g >> 2);
        bias_s[tid] = bih[p] + bhh[p];
        if (IS_L0) wx_s[tid] = Wih[p];
    }

    // ---- one-time: weights ----
    uint32_t bw[2][IS_L0 ? 16 : 1][2];
    if constexpr (IS_L0) {
        #pragma unroll
        for (int ni = 0; ni < 2; ni++) {
            int n_g = n0 + warp * 16 + ni * 8 + gid;
            int p   = (n_g & 3) * H_ + (n_g >> 2);
            const float* wr = Whh + (size_t)p * H_;
            #pragma unroll
            for (int kc = 0; kc < 16; kc++) {
                int k = kc * 16 + tig * 2;
                __half2 h01 = __floats2half2_rn(wr[k], wr[k + 1]);
                __half2 h89 = __floats2half2_rn(wr[k + 8], wr[k + 9]);
                bw[ni][kc][0] = *(uint32_t*)&h01;
                bw[ni][kc][1] = *(uint32_t*)&h89;
            }
        }
        if (tid < MT) xs[tid] = x[(size_t)(b0 + tid) * T_];   // x[:,0]
    } else {
        for (int idx = tid; idx < NT * KDIM; idx += THREADS) {
            int nl = idx / KDIM, k = idx % KDIM;
            int n_g = n0 + nl;
            int p   = (n_g & 3) * H_ + (n_g >> 2);
            float v = (k < H_) ? Wih[(size_t)p * H_ + k]
                               : Whh[(size_t)p * H_ + (k - H_)];
            Ws[nl * RS + k] = __float2half_rn(v);
        }
        // prologue: wait for y0[0], load into A's first H_ columns
        while (ld_acq(ctr_up) < (unsigned)NTILE) { }
        int row = tid >> 3, seg = tid & 7;
        const uint4* src = (const uint4*)(g_y0 + (size_t)(b0 + row) * H_ + seg * 32);
        uint4* dst = (uint4*)(As + row * RS + seg * 32);
        #pragma unroll
        for (int i = 0; i < 4; i++) dst[i] = src[i];
    }

    // ---- per-lane ldmatrix addresses ----
    const uint32_t As_b = smem_u32(As);
    uint32_t aAddr[2];
    #pragma unroll
    for (int mi = 0; mi < 2; mi++) {
        int rA = mi * 16 + (lane & 15);
        int cA = ((lane >> 4) & 1) * 8;
        aAddr[mi] = As_b + (uint32_t)(rA * RS + cA) * 2u;
    }
    uint32_t bAddr = 0;
    if constexpr (!IS_L0) {
        int rB = warp * 16 + (lane & 7) + ((lane & 16) ? 8 : 0);
        int cB = (lane & 8) ? 8 : 0;
        bAddr = smem_u32(Ws) + (uint32_t)(rB * RS + cB) * 2u;
    }

    const int m     = tid >> 3;          // epilogue batch row
    const int ubase = (tid & 7) * 4;     // epilogue first local unit
    float creg[4] = {0.f, 0.f, 0.f, 0.f};

    for (int t = 0; t < T_; ++t) {
        // ---- load h_prev into A's h-region ----
        {
            int row = tid >> 3, seg = tid & 7;
            const uint4* src = (const uint4*)(hbuf + (size_t)(t & 1) * (B_ * H_) +
                                              (size_t)(b0 + row) * H_ + seg * 32);
            uint4* dst = (uint4*)(As + row * RS + HOFF + seg * 32);
            #pragma unroll
            for (int i = 0; i < 4; i++) dst[i] = src[i];
        }
        __syncthreads();

        // ---- MMA: 32 x 128 gates, warp owns 16 N-cols ----
        float acc[2][2][4];
        #pragma unroll
        for (int mi = 0; mi < 2; mi++)
            #pragma unroll
            for (int ni = 0; ni < 2; ni++)
                #pragma unroll
                for (int r = 0; r < 4; r++) acc[mi][ni][r] = 0.f;

        #pragma unroll
        for (int kc = 0; kc < NKC; kc++) {
            uint32_t a0[4], a1[4];
            ldsm4(a0, aAddr[0] + kc * 32u);
            ldsm4(a1, aAddr[1] + kc * 32u);
            if constexpr (IS_L0) {
                mma16816(acc[0][0], a0, bw[0][kc][0], bw[0][kc][1]);
                mma16816(acc[0][1], a0, bw[1][kc][0], bw[1][kc][1]);
                mma16816(acc[1][0], a1, bw[0][kc][0], bw[0][kc][1]);
                mma16816(acc[1][1], a1, bw[1][kc][0], bw[1][kc][1]);
            } else {
                uint32_t bb[4];
                ldsm4(bb, bAddr + kc * 32u);
                mma16816(acc[0][0], a0, bb[0], bb[1]);
                mma16816(acc[0][1], a0, bb[2], bb[3]);
                mma16816(acc[1][0], a1, bb[0], bb[1]);
                mma16816(acc[1][1], a1, bb[2], bb[3]);
            }
        }

        // ---- dump to smem so each thread owns whole units ----
        #pragma unroll
        for (int mi = 0; mi < 2; mi++)
            #pragma unroll
            for (int ni = 0; ni < 2; ni++) {
                float* gp = Gs + (mi * 16 + gid) * GS + warp * 16 + ni * 8 + tig * 2;
                *(float2*)gp            = make_float2(acc[mi][ni][0], acc[mi][ni][1]);
                *(float2*)(gp + 8 * GS) = make_float2(acc[mi][ni][2], acc[mi][ni][3]);
            }
        __syncthreads();

        // ---- elementwise for 4 hidden units of one row ----
        float hv[4];
        float xv = IS_L0 ? xs[(t & 1) * MT + m] : 0.f;
        #pragma unroll
        for (int e = 0; e < 4; e++) {
            int nl = (ubase + e) * 4;
            const float4 gv = *(const float4*)(Gs + m * GS + nl);
            float pi = gv.x + bias_s[nl + 0];
            float pf = gv.y + bias_s[nl + 1];
            float pg = gv.z + bias_s[nl + 2];
            float po = gv.w + bias_s[nl + 3];
            if constexpr (IS_L0) {
                pi += xv * wx_s[nl + 0];
                pf += xv * wx_s[nl + 1];
                pg += xv * wx_s[nl + 2];
                po += xv * wx_s[nl + 3];
            }
            float ig = sig_hw(pi), fg = sig_hw(pf);
            float gg = tanh_hw(pg), og = sig_hw(po);
            float c  = fg * creg[e] + ig * gg;
            creg[e]  = c;
            hv[e]    = og * tanh_hw(c);
        }

        // ---- publish h_t (fp16); L0 also writes y0 ----
        __half2 p01 = __floats2half2_rn(hv[0], hv[1]);
        __half2 p23 = __floats2half2_rn(hv[2], hv[3]);
        uint2 pk = make_uint2(*(uint32_t*)&p01, *(uint32_t*)&p23);
        *(uint2*)(hbuf + (size_t)((t + 1) & 1) * (B_ * H_) +
                  (size_t)(b0 + m) * H_ + j0 + ubase) = pk;
        if constexpr (IS_L0) {
            *(uint2*)(g_y0 + ((size_t)t * B_ + b0 + m) * H_ + j0 + ubase) = pk;
        }
        if (t == T_ - 1) {
            size_t oidx = ((size_t)layer_idx * B_ + (b0 + m)) * H_ + j0 + ubase;
            *(float4*)(out + oidx) = make_float4(hv[0], hv[1], hv[2], hv[3]);
            *(float4*)(out + (size_t)2 * B_ * H_ + oidx) =
                make_float4(creg[0], creg[1], creg[2], creg[3]);
        }

        // ---- tail prefetch (off the h critical path) ----
        if (t + 1 < T_) {
            if constexpr (IS_L0) {
                if (tid < MT)
                    xs[((t + 1) & 1) * MT + tid] = x[(size_t)(b0 + tid) * T_ + (t + 1)];
            } else {
                // wait for producer step t+1, then prefetch y0[t+1]
                const unsigned need = (unsigned)NTILE * (unsigned)(t + 2);
                while (ld_acq(ctr_up) < need) { }
                int row = tid >> 3, seg = tid & 7;
                const uint4* src = (const uint4*)(g_y0 +
                    ((size_t)(t + 1) * B_ + b0 + row) * H_ + seg * 32);
                uint4* dst = (uint4*)(As + row * RS + seg * 32);
                #pragma unroll
                for (int i = 0; i < 4; i++) dst[i] = src[i];
            }
        }

        // ---- per-group barrier (monotonic counter, release/acquire) ----
        __syncthreads();
        if (tid == 0) {
            __threadfence();
            red_add_rel(ctr);
            const unsigned target = (unsigned)NTILE * (unsigned)(t + 1);
            while (ld_acq(ctr) < target) { }
        }
        __syncthreads();
    }
}

__global__ __launch_bounds__(THREADS, 1)
void lstm_fused_kernel(const float* __restrict__ x,
                       const float* __restrict__ Wih0, const float* __restrict__ Whh0,
                       const float* __restrict__ bih0, const float* __restrict__ bhh0,
                       const float* __restrict__ Wih1, const float* __restrict__ Whh1,
                       const float* __restrict__ bih1, const float* __restrict__ bhh1,
                       float* __restrict__ out) {
    if (blockIdx.z == 0)
        run_layer<256, true >(x, Wih0, Whh0, bih0, bhh0, out, 0);
    else
        run_layer<512, false>(nullptr, Wih1, Whh1, bih1, bhh1, out, 1);
}

extern "C" void kernel_launch(void* const* d_in, const int* in_sizes, int n_in,
                              void* d_out, int out_size) {
    (void)in_sizes; (void)n_in; (void)out_size;
    const float* x    = (const float*)d_in[0];
    const float* Wih0 = (const float*)d_in[1];
    const float* Whh0 = (const float*)d_in[2];
    const float* bih0 = (const float*)d_in[3];
    const float* bhh0 = (const float*)d_in[4];
    const float* Wih1 = (const float*)d_in[5];
    const float* Whh1 = (const float*)d_in[6];
    const float* bih1 = (const float*)d_in[7];
    const float* bhh1 = (const float*)d_in[8];
    float* out = (float*)d_out;

    // L1 smem footprint (the larger of the two layouts):
    // A [32][520] + W [128][520] halfs, G [32][132] floats, bias/wx/xs
    const int RS1 = 512 + 8, GS = NT + 4;
    const int smem_bytes = (MT + NT) * RS1 * 2 + MT * GS * 4 + (NT + NT + 2 * MT) * 4;

    cudaFuncSetAttribute((const void*)&lstm_fused_kernel,
                         cudaFuncAttributeMaxDynamicSharedMemorySize, smem_bytes);

    init_kernel<<<512, 256>>>();

    dim3 grid(NTILE, NGROUP, 2);
    lstm_fused_kernel<<<grid, THREADS, smem_bytes>>>(
        x, Wih0, Whh0, bih0, bhh0, Wih1, Whh1, bih1, bhh1, out);
}